// round 1
// baseline (speedup 1.0000x reference)
#include <cuda_runtime.h>

// LeiNet: head[b,n] = dot(x[n,b,:], head_w[n,:]) + head_b[n]
//         logits[b,k] = sum_n head[b,n]*foot_w[k,n] + foot_b[k]
//         out[b,:] = softmax(logits[b,:])  (2-way)
//
// x: [128, 4096, 512] fp32 (1.07 GB, streamed once)  -> HBM-bound kernel.

#define N_NEURON 128
#define N_RULES  512
#define THREADS  512
#define WARPS    (THREADS / 32)
#define NEURONS_PER_WARP (N_NEURON / WARPS)   // 8

__global__ __launch_bounds__(THREADS)
void leinet_kernel(const float* __restrict__ x,
                   const float* __restrict__ head_w,
                   const float* __restrict__ head_b,
                   const float* __restrict__ foot_w,
                   const float* __restrict__ foot_b,
                   float* __restrict__ out,
                   int batch)
{
    const int b    = blockIdx.x;
    const int tid  = threadIdx.x;
    const int wid  = tid >> 5;
    const int lane = tid & 31;

    __shared__ float head_s[N_NEURON];

    // Each warp computes 8 neuron dot-products of length 512.
    #pragma unroll
    for (int i = 0; i < NEURONS_PER_WARP; i++) {
        const int n = wid * NEURONS_PER_WARP + i;
        const float4* __restrict__ xr =
            reinterpret_cast<const float4*>(x + ((size_t)n * batch + b) * N_RULES);
        const float4* __restrict__ wr =
            reinterpret_cast<const float4*>(head_w + (size_t)n * N_RULES);

        // 512 floats = 128 float4 = 32 lanes * 4 iterations. Issue the 4
        // streaming loads back-to-back for MLP=4 before consuming.
        float4 xv0 = __ldcs(&xr[lane +  0]);
        float4 xv1 = __ldcs(&xr[lane + 32]);
        float4 xv2 = __ldcs(&xr[lane + 64]);
        float4 xv3 = __ldcs(&xr[lane + 96]);
        float4 wv0 = __ldg(&wr[lane +  0]);
        float4 wv1 = __ldg(&wr[lane + 32]);
        float4 wv2 = __ldg(&wr[lane + 64]);
        float4 wv3 = __ldg(&wr[lane + 96]);

        float s = xv0.x * wv0.x + xv0.y * wv0.y + xv0.z * wv0.z + xv0.w * wv0.w;
        s += xv1.x * wv1.x + xv1.y * wv1.y + xv1.z * wv1.z + xv1.w * wv1.w;
        s += xv2.x * wv2.x + xv2.y * wv2.y + xv2.z * wv2.z + xv2.w * wv2.w;
        s += xv3.x * wv3.x + xv3.y * wv3.y + xv3.z * wv3.z + xv3.w * wv3.w;

        // Warp butterfly reduction.
        #pragma unroll
        for (int o = 16; o > 0; o >>= 1)
            s += __shfl_xor_sync(0xFFFFFFFFu, s, o);

        if (lane == 0)
            head_s[n] = s + __ldg(&head_b[n]);
    }
    __syncthreads();

    // Warp 0: foot layer (2 x 128) + 2-way softmax.
    if (wid == 0) {
        float p0 = 0.f, p1 = 0.f;
        #pragma unroll
        for (int j = 0; j < 4; j++) {
            const int n = lane + 32 * j;
            const float h = head_s[n];
            p0 += h * __ldg(&foot_w[n]);             // foot_w[0][n]
            p1 += h * __ldg(&foot_w[N_NEURON + n]);  // foot_w[1][n]
        }
        #pragma unroll
        for (int o = 16; o > 0; o >>= 1) {
            p0 += __shfl_xor_sync(0xFFFFFFFFu, p0, o);
            p1 += __shfl_xor_sync(0xFFFFFFFFu, p1, o);
        }
        if (lane == 0) {
            p0 += __ldg(&foot_b[0]);
            p1 += __ldg(&foot_b[1]);
            const float m  = fmaxf(p0, p1);
            const float e0 = expf(p0 - m);
            const float e1 = expf(p1 - m);
            const float inv = 1.0f / (e0 + e1);
            out[2 * b + 0] = e0 * inv;
            out[2 * b + 1] = e1 * inv;
        }
    }
}

extern "C" void kernel_launch(void* const* d_in, const int* in_sizes, int n_in,
                              void* d_out, int out_size)
{
    const float* x      = (const float*)d_in[0];
    const float* head_w = (const float*)d_in[1];
    const float* head_b = (const float*)d_in[2];
    const float* foot_w = (const float*)d_in[3];
    const float* foot_b = (const float*)d_in[4];
    float* out = (float*)d_out;

    const int batch = in_sizes[0] / (N_NEURON * N_RULES);   // 4096

    leinet_kernel<<<batch, THREADS>>>(x, head_w, head_b, foot_w, foot_b, out, batch);
}

// round 2
// speedup vs baseline: 1.0014x; 1.0014x over previous
#include <cuda_runtime.h>

// LeiNet: head[b,n] = dot(x[n,b,:], head_w[n,:]) + head_b[n]
//         logits[b,k] = sum_n head[b,n]*foot_w[k,n] + foot_b[k]
//         out[b,:] = softmax(logits[b,:])  (2-way)
//
// x: [128, 4096, 512] fp32 (1.07 GB, streamed once) -> pure HBM-bound.
// R2: persistent grid (456 = 152 SMs x 3 CTAs), grid-stride over batch.
//     Removes ~9 wave transitions (~2360 cyc each) of DRAM idle.

#define N_NEURON 128
#define N_RULES  512
#define THREADS  512
#define WARPS    (THREADS / 32)
#define NEURONS_PER_WARP (N_NEURON / WARPS)   // 8
#define GRID_PERSIST 456                      // 152 SMs * 3 resident CTAs

__global__ __launch_bounds__(THREADS)
void leinet_kernel(const float* __restrict__ x,
                   const float* __restrict__ head_w,
                   const float* __restrict__ head_b,
                   const float* __restrict__ foot_w,
                   const float* __restrict__ foot_b,
                   float* __restrict__ out,
                   int batch)
{
    const int tid  = threadIdx.x;
    const int wid  = tid >> 5;
    const int lane = tid & 31;

    __shared__ float head_s[N_NEURON];

    for (int b = blockIdx.x; b < batch; b += gridDim.x) {

        // Each warp computes 8 neuron dot-products of length 512.
        #pragma unroll
        for (int i = 0; i < NEURONS_PER_WARP; i++) {
            const int n = wid * NEURONS_PER_WARP + i;
            const float4* __restrict__ xr =
                reinterpret_cast<const float4*>(x + ((size_t)n * batch + b) * N_RULES);
            const float4* __restrict__ wr =
                reinterpret_cast<const float4*>(head_w + (size_t)n * N_RULES);

            // 512 floats = 128 float4 = 32 lanes * 4 chunks. Streaming loads
            // for x (zero reuse); cached loads for head_w (L1-hot across the
            // persistent b-loop).
            float4 xv0 = __ldcs(&xr[lane +  0]);
            float4 xv1 = __ldcs(&xr[lane + 32]);
            float4 xv2 = __ldcs(&xr[lane + 64]);
            float4 xv3 = __ldcs(&xr[lane + 96]);
            float4 wv0 = __ldg(&wr[lane +  0]);
            float4 wv1 = __ldg(&wr[lane + 32]);
            float4 wv2 = __ldg(&wr[lane + 64]);
            float4 wv3 = __ldg(&wr[lane + 96]);

            float s = xv0.x * wv0.x + xv0.y * wv0.y + xv0.z * wv0.z + xv0.w * wv0.w;
            s += xv1.x * wv1.x + xv1.y * wv1.y + xv1.z * wv1.z + xv1.w * wv1.w;
            s += xv2.x * wv2.x + xv2.y * wv2.y + xv2.z * wv2.z + xv2.w * wv2.w;
            s += xv3.x * wv3.x + xv3.y * wv3.y + xv3.z * wv3.z + xv3.w * wv3.w;

            // Warp butterfly reduction.
            #pragma unroll
            for (int o = 16; o > 0; o >>= 1)
                s += __shfl_xor_sync(0xFFFFFFFFu, s, o);

            if (lane == 0)
                head_s[n] = s + __ldg(&head_b[n]);
        }
        __syncthreads();

        // Warp 0: foot layer (2 x 128) + 2-way softmax.
        if (wid == 0) {
            float p0 = 0.f, p1 = 0.f;
            #pragma unroll
            for (int j = 0; j < 4; j++) {
                const int n = lane + 32 * j;
                const float h = head_s[n];
                p0 += h * __ldg(&foot_w[n]);             // foot_w[0][n]
                p1 += h * __ldg(&foot_w[N_NEURON + n]);  // foot_w[1][n]
            }
            #pragma unroll
            for (int o = 16; o > 0; o >>= 1) {
                p0 += __shfl_xor_sync(0xFFFFFFFFu, p0, o);
                p1 += __shfl_xor_sync(0xFFFFFFFFu, p1, o);
            }
            if (lane == 0) {
                p0 += __ldg(&foot_b[0]);
                p1 += __ldg(&foot_b[1]);
                const float m  = fmaxf(p0, p1);
                const float e0 = expf(p0 - m);
                const float e1 = expf(p1 - m);
                const float inv = 1.0f / (e0 + e1);
                out[2 * b + 0] = e0 * inv;
                out[2 * b + 1] = e1 * inv;
            }
        }
        __syncthreads();   // protect head_s before next b iteration
    }
}

extern "C" void kernel_launch(void* const* d_in, const int* in_sizes, int n_in,
                              void* d_out, int out_size)
{
    const float* x      = (const float*)d_in[0];
    const float* head_w = (const float*)d_in[1];
    const float* head_b = (const float*)d_in[2];
    const float* foot_w = (const float*)d_in[3];
    const float* foot_b = (const float*)d_in[4];
    float* out = (float*)d_out;

    const int batch = in_sizes[0] / (N_NEURON * N_RULES);   // 4096

    const int grid = (batch < GRID_PERSIST) ? batch : GRID_PERSIST;
    leinet_kernel<<<grid, THREADS>>>(x, head_w, head_b, foot_w, foot_b, out, batch);
}